// round 6
// baseline (speedup 1.0000x reference)
#include <cuda_runtime.h>
#include <math.h>
#include <stdint.h>

#define NB 2
#define NC 64
#define HW 2304
#define INNER 64
#define HEADS 8
#define DH 8
#define MM 36
#define SCALE 0.35355339059327373f

// ---------------- scratch (device globals; no allocation allowed) ----------------
__device__ float g_qt[NB * HW * INNER];          // q channel-last: [b][p][c]
__device__ float g_kt[NB * HW * INNER];          // k channel-last: [b][p][c]
__device__ float4 g_vlo4[NB * HEADS * HW];       // v channels 0..3:  [b][head][j]
__device__ float4 g_vhi4[NB * HEADS * HW];       // v channels 4..7
__device__ float g_qd[NB * INNER * MM];          // conv+gelu(q): [b][oc][pos36]
__device__ float g_kd[NB * INNER * MM];
__device__ float g_dots[NB * HEADS * MM * MM];   // [b][head][i36][j36]

// ---------------- kernel A: 1x1 conv qkv + layout transforms ----------------
__global__ void qkv_kernel(const float* __restrict__ f, const float* __restrict__ wqkv) {
    __shared__ float sF[64 * 32];   // [c][pp]
    int b = blockIdx.x / 72;
    int p0 = (blockIdx.x % 72) * 32;

    for (int idx = threadIdx.x; idx < 64 * 32; idx += 256) {
        int c = idx >> 5, pp = idx & 31;
        sF[idx] = f[(b * 64 + c) * HW + p0 + pp];
    }
    __syncthreads();

    int pp = threadIdx.x & 31;
    int o0 = threadIdx.x >> 5;   // 0..7
    int p = p0 + pp;
    for (int o = o0; o < 192; o += 8) {
        const float* wr = wqkv + o * 64;
        float a0 = 0.f, a1 = 0.f, a2 = 0.f, a3 = 0.f;
        #pragma unroll
        for (int c = 0; c < 16; c++) {
            a0 = fmaf(__ldg(&wr[c]),      sF[c * 32 + pp],        a0);
            a1 = fmaf(__ldg(&wr[c + 16]), sF[(c + 16) * 32 + pp], a1);
            a2 = fmaf(__ldg(&wr[c + 32]), sF[(c + 32) * 32 + pp], a2);
            a3 = fmaf(__ldg(&wr[c + 48]), sF[(c + 48) * 32 + pp], a3);
        }
        float acc = (a0 + a1) + (a2 + a3);
        if (o < 64) {
            g_qt[(b * HW + p) * 64 + o] = acc;
        } else if (o < 128) {
            g_kt[(b * HW + p) * 64 + (o - 64)] = acc;
        } else {
            int oi = o - 128;
            int hd = oi >> 3, c = oi & 7;
            float* vout = (float*)(c < 4 ? g_vlo4 : g_vhi4);
            vout[((size_t)(b * HEADS + hd) * HW + p) * 4 + (c & 3)] = acc;
        }
    }
}

// ---------------- kernel B: 11x11 stride-8 pad-2 conv + exact GELU ----------------
// grid: 2 tensors * 2 b * 64 oc = 256 blocks, 288 threads (9 warps, 4 pos each)
__global__ void conv_kernel(const float* __restrict__ wq, const float* __restrict__ bq,
                            const float* __restrict__ wk, const float* __restrict__ bk) {
    int bid = blockIdx.x;
    int oc = bid & 63;
    int b  = (bid >> 6) & 1;
    int t  = bid >> 7;

    const float* wsrc = (t ? wk : wq) + oc * 64 * 121;   // layout [ic][tap], linear
    const float* in   = (t ? g_kt : g_qt) + b * HW * 64;

    __shared__ float sw[121 * 65];
    for (int idx = threadIdx.x; idx < 121 * 64; idx += 288) {
        int ic = idx / 121, tap = idx % 121;
        sw[tap * 65 + ic] = wsrc[idx];
    }
    __syncthreads();

    int warp = threadIdx.x >> 5, lane = threadIdx.x & 31;
    int pos0 = warp * 4;

    int ihb[4], iwb[4];
    #pragma unroll
    for (int r = 0; r < 4; r++) {
        int pos = pos0 + r;
        ihb[r] = (pos / 6) * 8 - 2;
        iwb[r] = (pos % 6) * 8 - 2;
    }

    float pa[4] = {0.f, 0.f, 0.f, 0.f}, pb[4] = {0.f, 0.f, 0.f, 0.f};
    #pragma unroll
    for (int kh = 0; kh < 11; kh++) {
        #pragma unroll
        for (int kw = 0; kw < 11; kw++) {
            const float* wp = sw + (kh * 11 + kw) * 65;
            float w0 = wp[lane], w1 = wp[lane + 32];
            #pragma unroll
            for (int r = 0; r < 4; r++) {
                int ih = ihb[r] + kh, iw = iwb[r] + kw;
                if ((unsigned)ih < 48u && (unsigned)iw < 48u) {
                    const float* ip = in + (ih * 48 + iw) * 64;
                    pa[r] = fmaf(ip[lane],      w0, pa[r]);
                    pb[r] = fmaf(ip[lane + 32], w1, pb[r]);
                }
            }
        }
    }
    float acc[4];
    #pragma unroll
    for (int r = 0; r < 4; r++) acc[r] = pa[r] + pb[r];
    #pragma unroll
    for (int off = 16; off; off >>= 1) {
        #pragma unroll
        for (int r = 0; r < 4; r++)
            acc[r] += __shfl_xor_sync(0xffffffffu, acc[r], off);
    }
    if (lane == 0) {
        float bias = (t ? bk : bq)[oc];
        float* dst = (t ? g_kd : g_qd) + (b * 64 + oc) * MM;
        #pragma unroll
        for (int r = 0; r < 4; r++) {
            float x = acc[r] + bias;
            dst[pos0 + r] = 0.5f * x * (1.0f + erff(x * 0.7071067811865476f));
        }
    }
}

// ---------------- kernel C: dots[b,h,i36,j36] ----------------
__global__ void dots_kernel() {
    int idx = blockIdx.x * 256 + threadIdx.x;
    if (idx >= NB * HEADS * MM * MM) return;
    int j  = idx % 36;
    int i  = (idx / 36) % 36;
    int bh = idx / (36 * 36);
    int b = bh >> 3, hd = bh & 7;
    const float* qd = g_qd + (b * 64 + hd * 8) * MM;
    const float* kd = g_kd + (b * 64 + hd * 8) * MM;
    float s = 0.f;
    #pragma unroll
    for (int c = 0; c < 8; c++) s = fmaf(qd[c * MM + i], kd[c * MM + j], s);
    g_dots[idx] = s * SCALE;
}

// ---------------- kernel D: fused pos-logits + softmax + attn@v ----------------
// one warp per 4 consecutive output rows; grid 1152 blocks, 256 threads

#define FMA2(d, a, b, c) asm("fma.rn.f32x2 %0, %1, %2, %3;" : "=l"(d) : "l"(a), "l"(b), "l"(c))
#define PACK2(out, x)    asm("mov.b64 %0, {%1, %1};" : "=l"(out) : "r"(x))
#define UNPK2(lo, hi, in) asm("mov.b64 {%0, %1}, %2;" : "=r"(lo), "=r"(hi) : "l"(in))

// per-warp smem floats: sQ 32 | sD 40 | sA 192 | sB 192 | eC2 576 = 1032
#define WSH 1032

__global__ void __launch_bounds__(256, 3)
attn_kernel(const float* __restrict__ pos_h, const float* __restrict__ pos_w,
            float* __restrict__ out) {
    __shared__ float sh[8][WSH];
    int warp = threadIdx.x >> 5, lane = threadIdx.x & 31;
    int w = blockIdx.x * 8 + warp;              // global warp id < 9216
    int bh = w / 576;
    int i0 = (w % 576) * 4;
    int b = bh >> 3, hd = bh & 7;

    float* sQ  = sh[warp];          // 32
    float* sD  = sh[warp] + 32;     // 40  (later reused as sumB16[12])
    float* sA  = sh[warp] + 72;     // 4*48
    float* sB  = sh[warp] + 264;    // 4*48
    float* eC2 = sh[warp] + 456;    // 144*4, layout [s][r]
    float* smB = sh[warp] + 32;     // alias sD: sumB16[r*3+phi]

    // stage q for 4 rows
    {
        int r = lane >> 3, c = lane & 7;
        sQ[lane] = g_qt[((size_t)(b * HW + i0 + r)) * 64 + hd * 8 + c];
    }
    // raw D row
    {
        const float* dsrc = g_dots + ((b * HEADS + hd) * MM + (i0 >> 6)) * MM;
        for (int t = lane; t < 36; t += 32) sD[t] = dsrc[t];
    }
    __syncwarp();

    // raw A/B for 4 rows
    for (int jh = lane; jh < 48; jh += 32) {
        #pragma unroll
        for (int r = 0; r < 4; r++) {
            float a = 0.f, bb = 0.f;
            #pragma unroll
            for (int c = 0; c < 8; c++) {
                float qv = sQ[r * 8 + c];
                a  = fmaf(qv, __ldg(&pos_h[c * 48 + jh]), a);
                bb = fmaf(qv, __ldg(&pos_w[c * 48 + jh]), bb);
            }
            sA[r * 48 + jh] = a;
            sB[r * 48 + jh] = bb;
        }
    }
    __syncwarp();

    // per-component maxes
    float mA[4], mB[4], mD = -1e30f;
    #pragma unroll
    for (int r = 0; r < 4; r++) { mA[r] = -1e30f; mB[r] = -1e30f; }
    for (int t = lane; t < 48; t += 32) {
        #pragma unroll
        for (int r = 0; r < 4; r++) {
            mA[r] = fmaxf(mA[r], sA[r * 48 + t]);
            mB[r] = fmaxf(mB[r], sB[r * 48 + t]);
        }
    }
    for (int t = lane; t < 36; t += 32) mD = fmaxf(mD, sD[t]);
    #pragma unroll
    for (int off = 16; off; off >>= 1) {
        mD = fmaxf(mD, __shfl_xor_sync(0xffffffffu, mD, off));
        #pragma unroll
        for (int r = 0; r < 4; r++) {
            mA[r] = fmaxf(mA[r], __shfl_xor_sync(0xffffffffu, mA[r], off));
            mB[r] = fmaxf(mB[r], __shfl_xor_sync(0xffffffffu, mB[r], off));
        }
    }
    __syncwarp();

    // exponentiate components in place
    for (int t = lane; t < 36; t += 32) sD[t] = __expf(sD[t] - mD);
    for (int t = lane; t < 48; t += 32) {
        #pragma unroll
        for (int r = 0; r < 4; r++) {
            sA[r * 48 + t] = __expf(sA[r * 48 + t] - mA[r]);
            sB[r * 48 + t] = __expf(sB[r * 48 + t] - mB[r]);
        }
    }
    __syncwarp();

    // eC2[s][r] = eA[r][s/3] * eD[s>>2]   (s = j>>4; 16-segments align with both maps)
    for (int s = lane; s < 144; s += 32) {
        float d = sD[s >> 2];
        int jh = s / 3;
        float4 v;
        v.x = sA[0 * 48 + jh] * d;
        v.y = sA[1 * 48 + jh] * d;
        v.z = sA[2 * 48 + jh] * d;
        v.w = sA[3 * 48 + jh] * d;
        *(float4*)&eC2[s * 4] = v;
    }
    __syncwarp();

    // b-values this lane will ever need: jw = (lane + 32t) % 48 has period 3
    // phases: w0 = lane, w1 = (lane+32)%48, w2 = lane+16
    int w0 = lane;
    int w1 = (lane < 16) ? lane + 32 : lane - 16;
    int w2 = lane + 16;
    float bv0[3], bv1[3], bv2[3], bv3[3];
    bv0[0] = sB[0 * 48 + w0]; bv0[1] = sB[0 * 48 + w1]; bv0[2] = sB[0 * 48 + w2];
    bv1[0] = sB[1 * 48 + w0]; bv1[1] = sB[1 * 48 + w1]; bv1[2] = sB[1 * 48 + w2];
    bv2[0] = sB[2 * 48 + w0]; bv2[1] = sB[2 * 48 + w1]; bv2[2] = sB[2 * 48 + w2];
    bv3[0] = sB[3 * 48 + w0]; bv3[1] = sB[3 * 48 + w1]; bv3[2] = sB[3 * 48 + w2];

    // sumB16[r][phi] = sum_{u<16} eB[r][16*phi+u]  (into sD region; sD dead now)
    if (lane < 12) {
        int r = lane / 3, phi = lane % 3;
        float s16 = 0.f;
        #pragma unroll
        for (int u = 0; u < 16; u++) s16 += sB[r * 48 + phi * 16 + u];
        smB[r * 3 + phi] = s16;
    }
    __syncwarp();

    // per-lane partial row sums: ssum[r] = sum_s eC2[s][r] * sumB16[r][s%3]
    float ssum[4] = {0.f, 0.f, 0.f, 0.f};
    for (int s = lane; s < 144; s += 32) {
        int phi = s % 3;
        float4 c = *(const float4*)&eC2[s * 4];
        ssum[0] = fmaf(c.x, smB[0 + phi], ssum[0]);
        ssum[1] = fmaf(c.y, smB[3 + phi], ssum[1]);
        ssum[2] = fmaf(c.z, smB[6 + phi], ssum[2]);
        ssum[3] = fmaf(c.w, smB[9 + phi], ssum[3]);
    }

    const ulonglong2* vlo = (const ulonglong2*)g_vlo4 + (size_t)(b * HEADS + hd) * HW;
    const ulonglong2* vhi = (const ulonglong2*)g_vhi4 + (size_t)(b * HEADS + hd) * HW;

    unsigned long long acc[4][4];
    #pragma unroll
    for (int r = 0; r < 4; r++)
        #pragma unroll
        for (int k = 0; k < 4; k++) acc[r][k] = 0ull;

    // main loop: j = lane + 32t, t = 0..71; unroll 3 so phase = t%3 is static.
    // s = (lane>>4) + 2t.
    int j = lane;
    int s = lane >> 4;

#define STEP(JOFS, SOFS, PH) { \
        ulonglong2 L = vlo[j + (JOFS)]; \
        ulonglong2 H = vhi[j + (JOFS)]; \
        float4 c = *(const float4*)&eC2[(s + (SOFS)) * 4]; \
        float p0 = c.x * bv0[PH]; \
        float p1 = c.y * bv1[PH]; \
        float p2 = c.z * bv2[PH]; \
        float p3 = c.w * bv3[PH]; \
        unsigned long long q0, q1, q2, q3; \
        PACK2(q0, __float_as_uint(p0)); \
        PACK2(q1, __float_as_uint(p1)); \
        PACK2(q2, __float_as_uint(p2)); \
        PACK2(q3, __float_as_uint(p3)); \
        FMA2(acc[0][0], q0, L.x, acc[0][0]); FMA2(acc[0][1], q0, L.y, acc[0][1]); \
        FMA2(acc[0][2], q0, H.x, acc[0][2]); FMA2(acc[0][3], q0, H.y, acc[0][3]); \
        FMA2(acc[1][0], q1, L.x, acc[1][0]); FMA2(acc[1][1], q1, L.y, acc[1][1]); \
        FMA2(acc[1][2], q1, H.x, acc[1][2]); FMA2(acc[1][3], q1, H.y, acc[1][3]); \
        FMA2(acc[2][0], q2, L.x, acc[2][0]); FMA2(acc[2][1], q2, L.y, acc[2][1]); \
        FMA2(acc[2][2], q2, H.x, acc[2][2]); FMA2(acc[2][3], q2, H.y, acc[2][3]); \
        FMA2(acc[3][0], q3, L.x, acc[3][0]); FMA2(acc[3][1], q3, L.y, acc[3][1]); \
        FMA2(acc[3][2], q3, H.x, acc[3][2]); FMA2(acc[3][3], q3, H.y, acc[3][3]); \
    }

    #pragma unroll 1
    for (int tt = 0; tt < 24; tt++) {
        STEP(0,  0, 0)
        STEP(32, 2, 1)
        STEP(64, 4, 2)
        j += 96;
        s += 6;
    }
#undef STEP

    // reduce + write 4 rows
    #pragma unroll
    for (int r = 0; r < 4; r++) {
        float f0, f1, f2, f3, f4, f5, f6, f7;
        unsigned u0, u1;
        UNPK2(u0, u1, acc[r][0]); f0 = __uint_as_float(u0); f1 = __uint_as_float(u1);
        UNPK2(u0, u1, acc[r][1]); f2 = __uint_as_float(u0); f3 = __uint_as_float(u1);
        UNPK2(u0, u1, acc[r][2]); f4 = __uint_as_float(u0); f5 = __uint_as_float(u1);
        UNPK2(u0, u1, acc[r][3]); f6 = __uint_as_float(u0); f7 = __uint_as_float(u1);
        float sv = ssum[r];
        #pragma unroll
        for (int off = 16; off; off >>= 1) {
            sv += __shfl_xor_sync(0xffffffffu, sv, off);
            f0 += __shfl_xor_sync(0xffffffffu, f0, off);
            f1 += __shfl_xor_sync(0xffffffffu, f1, off);
            f2 += __shfl_xor_sync(0xffffffffu, f2, off);
            f3 += __shfl_xor_sync(0xffffffffu, f3, off);
            f4 += __shfl_xor_sync(0xffffffffu, f4, off);
            f5 += __shfl_xor_sync(0xffffffffu, f5, off);
            f6 += __shfl_xor_sync(0xffffffffu, f6, off);
            f7 += __shfl_xor_sync(0xffffffffu, f7, off);
        }
        float rr = f0;
        if (lane == 1) rr = f1;
        if (lane == 2) rr = f2;
        if (lane == 3) rr = f3;
        if (lane == 4) rr = f4;
        if (lane == 5) rr = f5;
        if (lane == 6) rr = f6;
        if (lane == 7) rr = f7;
        if (lane < 8)
            out[((size_t)(b * 64) + hd * 8 + lane) * HW + i0 + r] = rr / sv;
    }
}

// ---------------- launch ----------------
extern "C" void kernel_launch(void* const* d_in, const int* in_sizes, int n_in,
                              void* d_out, int out_size) {
    const float* f    = (const float*)d_in[0];
    const float* wqkv = (const float*)d_in[1];
    const float* wq   = (const float*)d_in[2];
    const float* bq   = (const float*)d_in[3];
    const float* wk   = (const float*)d_in[4];
    const float* bk   = (const float*)d_in[5];
    const float* ph   = (const float*)d_in[6];
    const float* pw   = (const float*)d_in[7];
    float* out = (float*)d_out;

    qkv_kernel<<<144, 256>>>(f, wqkv);
    conv_kernel<<<256, 288>>>(wq, bq, wk, bk);
    dots_kernel<<<81, 256>>>();
    attn_kernel<<<1152, 256>>>(ph, pw, out);
}

// round 7
// speedup vs baseline: 1.3880x; 1.3880x over previous
#include <cuda_runtime.h>
#include <math.h>
#include <stdint.h>

#define NB 2
#define NC 64
#define HW 2304
#define INNER 64
#define HEADS 8
#define DH 8
#define MM 36
#define SCALE 0.35355339059327373f

// ---------------- scratch (device globals; no allocation allowed) ----------------
__device__ float g_qt[NB * HW * INNER];          // q channel-last: [b][p][c]
__device__ float g_kt[NB * HW * INNER];          // k channel-last: [b][p][c]
__device__ float4 g_vlo4[NB * HEADS * HW];       // v channels 0..3:  [b][head][j]
__device__ float4 g_vhi4[NB * HEADS * HW];       // v channels 4..7
__device__ float g_qd[NB * INNER * MM];          // conv+gelu(q): [b][oc][pos36]
__device__ float g_kd[NB * INNER * MM];
__device__ float g_dots[NB * HEADS * MM * MM];   // [b][head][i36][j36]

// ---------------- kernel A: 1x1 conv qkv + layout transforms ----------------
__global__ void qkv_kernel(const float* __restrict__ f, const float* __restrict__ wqkv) {
    __shared__ float sF[64 * 32];   // [c][pp]
    int b = blockIdx.x / 72;
    int p0 = (blockIdx.x % 72) * 32;

    for (int idx = threadIdx.x; idx < 64 * 32; idx += 256) {
        int c = idx >> 5, pp = idx & 31;
        sF[idx] = f[(b * 64 + c) * HW + p0 + pp];
    }
    __syncthreads();

    int pp = threadIdx.x & 31;
    int o0 = threadIdx.x >> 5;   // 0..7
    int p = p0 + pp;
    for (int o = o0; o < 192; o += 8) {
        const float* wr = wqkv + o * 64;
        float a0 = 0.f, a1 = 0.f, a2 = 0.f, a3 = 0.f;
        #pragma unroll
        for (int c = 0; c < 16; c++) {
            a0 = fmaf(__ldg(&wr[c]),      sF[c * 32 + pp],        a0);
            a1 = fmaf(__ldg(&wr[c + 16]), sF[(c + 16) * 32 + pp], a1);
            a2 = fmaf(__ldg(&wr[c + 32]), sF[(c + 32) * 32 + pp], a2);
            a3 = fmaf(__ldg(&wr[c + 48]), sF[(c + 48) * 32 + pp], a3);
        }
        float acc = (a0 + a1) + (a2 + a3);
        if (o < 64) {
            g_qt[(b * HW + p) * 64 + o] = acc;
        } else if (o < 128) {
            g_kt[(b * HW + p) * 64 + (o - 64)] = acc;
        } else {
            int oi = o - 128;
            int hd = oi >> 3, c = oi & 7;
            float* vout = (float*)(c < 4 ? g_vlo4 : g_vhi4);
            vout[((size_t)(b * HEADS + hd) * HW + p) * 4 + (c & 3)] = acc;
        }
    }
}

// ---------------- kernel B: 11x11 stride-8 pad-2 conv + exact GELU ----------------
// grid: 2 tensors * 2 b * 64 oc * 2 pos-halves = 512 blocks, 288 threads (9 warps, 2 pos each)
__global__ void conv_kernel(const float* __restrict__ wq, const float* __restrict__ bq,
                            const float* __restrict__ wk, const float* __restrict__ bk) {
    int bid = blockIdx.x;
    int half = bid & 1;
    int oc = (bid >> 1) & 63;
    int b  = (bid >> 7) & 1;
    int t  = bid >> 8;

    const float* wsrc = (t ? wk : wq) + oc * 64 * 121;   // layout [ic][tap], linear
    const float* in   = (t ? g_kt : g_qt) + b * HW * 64;

    __shared__ float sw[121 * 65];
    for (int idx = threadIdx.x; idx < 121 * 64; idx += 288) {
        int ic = idx / 121, tap = idx % 121;
        sw[tap * 65 + ic] = wsrc[idx];
    }
    __syncthreads();

    int warp = threadIdx.x >> 5, lane = threadIdx.x & 31;
    int pos0 = half * 18 + warp * 2;

    int oh0 = pos0 / 6, ow0 = pos0 % 6;
    int oh1 = (pos0 + 1) / 6, ow1 = (pos0 + 1) % 6;
    int ihb0 = oh0 * 8 - 2, iwb0 = ow0 * 8 - 2;
    int ihb1 = oh1 * 8 - 2, iwb1 = ow1 * 8 - 2;

    float p0a = 0.f, p0b = 0.f, p1a = 0.f, p1b = 0.f;
    #pragma unroll
    for (int kh = 0; kh < 11; kh++) {
        #pragma unroll
        for (int kw = 0; kw < 11; kw++) {
            const float* wp = sw + (kh * 11 + kw) * 65;
            float w0 = wp[lane], w1 = wp[lane + 32];
            int ih0 = ihb0 + kh, iw0 = iwb0 + kw;
            if ((unsigned)ih0 < 48u && (unsigned)iw0 < 48u) {
                const float* ip = in + (ih0 * 48 + iw0) * 64;
                p0a = fmaf(ip[lane], w0, p0a);
                p0b = fmaf(ip[lane + 32], w1, p0b);
            }
            int ih1 = ihb1 + kh, iw1 = iwb1 + kw;
            if ((unsigned)ih1 < 48u && (unsigned)iw1 < 48u) {
                const float* ip = in + (ih1 * 48 + iw1) * 64;
                p1a = fmaf(ip[lane], w0, p1a);
                p1b = fmaf(ip[lane + 32], w1, p1b);
            }
        }
    }
    float acc0 = p0a + p0b;
    float acc1 = p1a + p1b;
    #pragma unroll
    for (int off = 16; off; off >>= 1) {
        acc0 += __shfl_xor_sync(0xffffffffu, acc0, off);
        acc1 += __shfl_xor_sync(0xffffffffu, acc1, off);
    }
    if (lane == 0) {
        float bias = (t ? bk : bq)[oc];
        float* dst = (t ? g_kd : g_qd) + (b * 64 + oc) * MM;
        float x0 = acc0 + bias;
        dst[pos0] = 0.5f * x0 * (1.0f + erff(x0 * 0.7071067811865476f));
        float x1 = acc1 + bias;
        dst[pos0 + 1] = 0.5f * x1 * (1.0f + erff(x1 * 0.7071067811865476f));
    }
}

// ---------------- kernel C: dots[b,h,i36,j36] ----------------
__global__ void dots_kernel() {
    int idx = blockIdx.x * 256 + threadIdx.x;
    if (idx >= NB * HEADS * MM * MM) return;
    int j  = idx % 36;
    int i  = (idx / 36) % 36;
    int bh = idx / (36 * 36);
    int b = bh >> 3, hd = bh & 7;
    const float* qd = g_qd + (b * 64 + hd * 8) * MM;
    const float* kd = g_kd + (b * 64 + hd * 8) * MM;
    float s = 0.f;
    #pragma unroll
    for (int c = 0; c < 8; c++) s = fmaf(qd[c * MM + i], kd[c * MM + j], s);
    g_dots[idx] = s * SCALE;
}

// ---------------- kernel D: fused pos-logits + softmax + attn@v ----------------
// one warp per 4 consecutive output rows; grid 1152 blocks, 256 threads

#define FMA2(d, a, b, c) asm("fma.rn.f32x2 %0, %1, %2, %3;" : "=l"(d) : "l"(a), "l"(b), "l"(c))
#define PACK2(out, x)    asm("mov.b64 %0, {%1, %1};" : "=l"(out) : "r"(x))
#define UNPK2(lo, hi, in) asm("mov.b64 {%0, %1}, %2;" : "=r"(lo), "=r"(hi) : "l"(in))

// per-warp smem floats: sQ 32 | sD 40 | sA 192 | sB 192 | eC2 576 = 1032
#define WSH 1032

__global__ void __launch_bounds__(256, 4)
attn_kernel(const float* __restrict__ pos_h, const float* __restrict__ pos_w,
            float* __restrict__ out) {
    __shared__ float sh[8][WSH];
    int warp = threadIdx.x >> 5, lane = threadIdx.x & 31;
    int w = blockIdx.x * 8 + warp;              // global warp id < 9216
    int bh = w / 576;
    int i0 = (w % 576) * 4;
    int b = bh >> 3, hd = bh & 7;

    float* sQ  = sh[warp];          // 32
    float* sD  = sh[warp] + 32;     // 40  (later reused as sumB16[12])
    float* sA  = sh[warp] + 72;     // 4*48
    float* sB  = sh[warp] + 264;    // 4*48
    float* eC2 = sh[warp] + 456;    // 144*4, layout [s][r]
    float* smB = sh[warp] + 32;     // alias sD: sumB16[r*3+phi]

    // stage q for 4 rows
    {
        int r = lane >> 3, c = lane & 7;
        sQ[lane] = g_qt[((size_t)(b * HW + i0 + r)) * 64 + hd * 8 + c];
    }
    // raw D row
    {
        const float* dsrc = g_dots + ((b * HEADS + hd) * MM + (i0 >> 6)) * MM;
        for (int t = lane; t < 36; t += 32) sD[t] = dsrc[t];
    }
    __syncwarp();

    // raw A/B for 4 rows
    for (int jh = lane; jh < 48; jh += 32) {
        #pragma unroll
        for (int r = 0; r < 4; r++) {
            float a = 0.f, bb = 0.f;
            #pragma unroll
            for (int c = 0; c < 8; c++) {
                float qv = sQ[r * 8 + c];
                a  = fmaf(qv, __ldg(&pos_h[c * 48 + jh]), a);
                bb = fmaf(qv, __ldg(&pos_w[c * 48 + jh]), bb);
            }
            sA[r * 48 + jh] = a;
            sB[r * 48 + jh] = bb;
        }
    }
    __syncwarp();

    // per-component maxes
    float mA[4], mB[4], mD = -1e30f;
    #pragma unroll
    for (int r = 0; r < 4; r++) { mA[r] = -1e30f; mB[r] = -1e30f; }
    for (int t = lane; t < 48; t += 32) {
        #pragma unroll
        for (int r = 0; r < 4; r++) {
            mA[r] = fmaxf(mA[r], sA[r * 48 + t]);
            mB[r] = fmaxf(mB[r], sB[r * 48 + t]);
        }
    }
    for (int t = lane; t < 36; t += 32) mD = fmaxf(mD, sD[t]);
    #pragma unroll
    for (int off = 16; off; off >>= 1) {
        mD = fmaxf(mD, __shfl_xor_sync(0xffffffffu, mD, off));
        #pragma unroll
        for (int r = 0; r < 4; r++) {
            mA[r] = fmaxf(mA[r], __shfl_xor_sync(0xffffffffu, mA[r], off));
            mB[r] = fmaxf(mB[r], __shfl_xor_sync(0xffffffffu, mB[r], off));
        }
    }
    __syncwarp();

    // exponentiate components in place
    for (int t = lane; t < 36; t += 32) sD[t] = __expf(sD[t] - mD);
    for (int t = lane; t < 48; t += 32) {
        #pragma unroll
        for (int r = 0; r < 4; r++) {
            sA[r * 48 + t] = __expf(sA[r * 48 + t] - mA[r]);
            sB[r * 48 + t] = __expf(sB[r * 48 + t] - mB[r]);
        }
    }
    __syncwarp();

    // eC2[s][r] = eA[r][s/3] * eD[s>>2]   (s = j>>4; 16-segments align with both maps)
    for (int s = lane; s < 144; s += 32) {
        float d = sD[s >> 2];
        int jh = s / 3;
        float4 v;
        v.x = sA[0 * 48 + jh] * d;
        v.y = sA[1 * 48 + jh] * d;
        v.z = sA[2 * 48 + jh] * d;
        v.w = sA[3 * 48 + jh] * d;
        *(float4*)&eC2[s * 4] = v;
    }
    __syncwarp();

    // b-values this lane will ever need: jw = (lane + 32t) % 48 has period 3
    // phases: w0 = lane, w1 = (lane+32)%48, w2 = lane+16
    int w0 = lane;
    int w1 = (lane < 16) ? lane + 32 : lane - 16;
    int w2 = lane + 16;
    float bv0[3], bv1[3], bv2[3], bv3[3];
    bv0[0] = sB[0 * 48 + w0]; bv0[1] = sB[0 * 48 + w1]; bv0[2] = sB[0 * 48 + w2];
    bv1[0] = sB[1 * 48 + w0]; bv1[1] = sB[1 * 48 + w1]; bv1[2] = sB[1 * 48 + w2];
    bv2[0] = sB[2 * 48 + w0]; bv2[1] = sB[2 * 48 + w1]; bv2[2] = sB[2 * 48 + w2];
    bv3[0] = sB[3 * 48 + w0]; bv3[1] = sB[3 * 48 + w1]; bv3[2] = sB[3 * 48 + w2];

    // sumB16[r][phi] = sum_{u<16} eB[r][16*phi+u]  (into sD region; sD dead now)
    if (lane < 12) {
        int r = lane / 3, phi = lane % 3;
        float s16 = 0.f;
        #pragma unroll
        for (int u = 0; u < 16; u++) s16 += sB[r * 48 + phi * 16 + u];
        smB[r * 3 + phi] = s16;
    }
    __syncwarp();

    // per-lane partial row sums: ssum[r] = sum_s eC2[s][r] * sumB16[r][s%3]
    float ssum[4] = {0.f, 0.f, 0.f, 0.f};
    for (int s = lane; s < 144; s += 32) {
        int phi = s % 3;
        float4 c = *(const float4*)&eC2[s * 4];
        ssum[0] = fmaf(c.x, smB[0 + phi], ssum[0]);
        ssum[1] = fmaf(c.y, smB[3 + phi], ssum[1]);
        ssum[2] = fmaf(c.z, smB[6 + phi], ssum[2]);
        ssum[3] = fmaf(c.w, smB[9 + phi], ssum[3]);
    }

    const ulonglong2* vlo = (const ulonglong2*)g_vlo4 + (size_t)(b * HEADS + hd) * HW;
    const ulonglong2* vhi = (const ulonglong2*)g_vhi4 + (size_t)(b * HEADS + hd) * HW;

    unsigned long long acc[4][4];
    #pragma unroll
    for (int r = 0; r < 4; r++)
        #pragma unroll
        for (int k = 0; k < 4; k++) acc[r][k] = 0ull;

    // main loop: j = lane + 32t, t = 0..71; unroll 3 so phase = t%3 is static.
    // s = (lane>>4) + 2t.
    int j = lane;
    int s = lane >> 4;

#define STEP(JOFS, SOFS, PH) { \
        ulonglong2 L = vlo[j + (JOFS)]; \
        ulonglong2 H = vhi[j + (JOFS)]; \
        float4 c = *(const float4*)&eC2[(s + (SOFS)) * 4]; \
        float p0 = c.x * bv0[PH]; \
        float p1 = c.y * bv1[PH]; \
        float p2 = c.z * bv2[PH]; \
        float p3 = c.w * bv3[PH]; \
        unsigned long long q0, q1, q2, q3; \
        PACK2(q0, __float_as_uint(p0)); \
        PACK2(q1, __float_as_uint(p1)); \
        PACK2(q2, __float_as_uint(p2)); \
        PACK2(q3, __float_as_uint(p3)); \
        FMA2(acc[0][0], q0, L.x, acc[0][0]); FMA2(acc[0][1], q0, L.y, acc[0][1]); \
        FMA2(acc[0][2], q0, H.x, acc[0][2]); FMA2(acc[0][3], q0, H.y, acc[0][3]); \
        FMA2(acc[1][0], q1, L.x, acc[1][0]); FMA2(acc[1][1], q1, L.y, acc[1][1]); \
        FMA2(acc[1][2], q1, H.x, acc[1][2]); FMA2(acc[1][3], q1, H.y, acc[1][3]); \
        FMA2(acc[2][0], q2, L.x, acc[2][0]); FMA2(acc[2][1], q2, L.y, acc[2][1]); \
        FMA2(acc[2][2], q2, H.x, acc[2][2]); FMA2(acc[2][3], q2, H.y, acc[2][3]); \
        FMA2(acc[3][0], q3, L.x, acc[3][0]); FMA2(acc[3][1], q3, L.y, acc[3][1]); \
        FMA2(acc[3][2], q3, H.x, acc[3][2]); FMA2(acc[3][3], q3, H.y, acc[3][3]); \
    }

    #pragma unroll 1
    for (int tt = 0; tt < 24; tt++) {
        STEP(0,  0, 0)
        STEP(32, 2, 1)
        STEP(64, 4, 2)
        j += 96;
        s += 6;
    }
#undef STEP

    // reduce + write 4 rows
    #pragma unroll
    for (int r = 0; r < 4; r++) {
        float f0, f1, f2, f3, f4, f5, f6, f7;
        unsigned u0, u1;
        UNPK2(u0, u1, acc[r][0]); f0 = __uint_as_float(u0); f1 = __uint_as_float(u1);
        UNPK2(u0, u1, acc[r][1]); f2 = __uint_as_float(u0); f3 = __uint_as_float(u1);
        UNPK2(u0, u1, acc[r][2]); f4 = __uint_as_float(u0); f5 = __uint_as_float(u1);
        UNPK2(u0, u1, acc[r][3]); f6 = __uint_as_float(u0); f7 = __uint_as_float(u1);
        float sv = ssum[r];
        #pragma unroll
        for (int off = 16; off; off >>= 1) {
            sv += __shfl_xor_sync(0xffffffffu, sv, off);
            f0 += __shfl_xor_sync(0xffffffffu, f0, off);
            f1 += __shfl_xor_sync(0xffffffffu, f1, off);
            f2 += __shfl_xor_sync(0xffffffffu, f2, off);
            f3 += __shfl_xor_sync(0xffffffffu, f3, off);
            f4 += __shfl_xor_sync(0xffffffffu, f4, off);
            f5 += __shfl_xor_sync(0xffffffffu, f5, off);
            f6 += __shfl_xor_sync(0xffffffffu, f6, off);
            f7 += __shfl_xor_sync(0xffffffffu, f7, off);
        }
        float rr = f0;
        if (lane == 1) rr = f1;
        if (lane == 2) rr = f2;
        if (lane == 3) rr = f3;
        if (lane == 4) rr = f4;
        if (lane == 5) rr = f5;
        if (lane == 6) rr = f6;
        if (lane == 7) rr = f7;
        if (lane < 8)
            out[((size_t)(b * 64) + hd * 8 + lane) * HW + i0 + r] = rr / sv;
    }
}

// ---------------- launch ----------------
extern "C" void kernel_launch(void* const* d_in, const int* in_sizes, int n_in,
                              void* d_out, int out_size) {
    const float* f    = (const float*)d_in[0];
    const float* wqkv = (const float*)d_in[1];
    const float* wq   = (const float*)d_in[2];
    const float* bq   = (const float*)d_in[3];
    const float* wk   = (const float*)d_in[4];
    const float* bk   = (const float*)d_in[5];
    const float* ph   = (const float*)d_in[6];
    const float* pw   = (const float*)d_in[7];
    float* out = (float*)d_out;

    qkv_kernel<<<144, 256>>>(f, wqkv);
    conv_kernel<<<512, 288>>>(wq, bq, wk, bk);
    dots_kernel<<<81, 256>>>();
    attn_kernel<<<1152, 256>>>(ph, pw, out);
}

// round 8
// speedup vs baseline: 1.5034x; 1.0832x over previous
#include <cuda_runtime.h>
#include <math.h>
#include <stdint.h>

#define NB 2
#define NC 64
#define HW 2304
#define INNER 64
#define HEADS 8
#define DH 8
#define MM 36
#define SCALE 0.35355339059327373f

// ---------------- scratch (device globals; no allocation allowed) ----------------
__device__ float g_qt[NB * HW * INNER];          // q channel-last: [b][p][c]
__device__ float g_kt[NB * HW * INNER];          // k channel-last: [b][p][c]
__device__ float4 g_vlo4[NB * HEADS * HW];       // v channels 0..3:  [b][head][j]
__device__ float4 g_vhi4[NB * HEADS * HW];       // v channels 4..7
__device__ float g_qd[NB * INNER * MM];          // conv+gelu(q): [b][oc][pos36]
__device__ float g_kd[NB * INNER * MM];
__device__ float g_dots[NB * HEADS * MM * MM];   // [b][head][i36][j36]

// ---------------- kernel A: 1x1 conv qkv + layout transforms ----------------
__global__ void qkv_kernel(const float* __restrict__ f, const float* __restrict__ wqkv) {
    __shared__ float sF[64 * 32];   // [c][pp]
    int b = blockIdx.x / 72;
    int p0 = (blockIdx.x % 72) * 32;

    for (int idx = threadIdx.x; idx < 64 * 32; idx += 256) {
        int c = idx >> 5, pp = idx & 31;
        sF[idx] = f[(b * 64 + c) * HW + p0 + pp];
    }
    __syncthreads();

    int pp = threadIdx.x & 31;
    int o0 = threadIdx.x >> 5;   // 0..7
    int p = p0 + pp;
    for (int o = o0; o < 192; o += 8) {
        const float* wr = wqkv + o * 64;
        float a0 = 0.f, a1 = 0.f, a2 = 0.f, a3 = 0.f;
        #pragma unroll
        for (int c = 0; c < 16; c++) {
            a0 = fmaf(__ldg(&wr[c]),      sF[c * 32 + pp],        a0);
            a1 = fmaf(__ldg(&wr[c + 16]), sF[(c + 16) * 32 + pp], a1);
            a2 = fmaf(__ldg(&wr[c + 32]), sF[(c + 32) * 32 + pp], a2);
            a3 = fmaf(__ldg(&wr[c + 48]), sF[(c + 48) * 32 + pp], a3);
        }
        float acc = (a0 + a1) + (a2 + a3);
        if (o < 64) {
            g_qt[(b * HW + p) * 64 + o] = acc;
        } else if (o < 128) {
            g_kt[(b * HW + p) * 64 + (o - 64)] = acc;
        } else {
            int oi = o - 128;
            int hd = oi >> 3, c = oi & 7;
            float* vout = (float*)(c < 4 ? g_vlo4 : g_vhi4);
            vout[((size_t)(b * HEADS + hd) * HW + p) * 4 + (c & 3)] = acc;
        }
    }
}

// ---------------- kernel B: 11x11 stride-8 pad-2 conv + exact GELU ----------------
// grid: 2 tensors * 2 b * 64 oc * 2 pos-halves = 512 blocks, 288 threads (9 warps, 2 pos each)
// float2-vectorized: lane covers ic = {2*lane, 2*lane+1}
__global__ void conv_kernel(const float* __restrict__ wq, const float* __restrict__ bq,
                            const float* __restrict__ wk, const float* __restrict__ bk) {
    int bid = blockIdx.x;
    int half = bid & 1;
    int oc = (bid >> 1) & 63;
    int b  = (bid >> 7) & 1;
    int t  = bid >> 8;

    const float* wsrc = (t ? wk : wq) + oc * 64 * 121;   // layout [ic][tap], linear
    const float* in   = (t ? g_kt : g_qt) + b * HW * 64;

    __shared__ __align__(16) float sw[121 * 66];   // [tap][ic], pad 66 keeps float2 aligned
    for (int idx = threadIdx.x; idx < 121 * 64; idx += 288) {
        int ic = idx / 121, tap = idx % 121;
        sw[tap * 66 + ic] = wsrc[idx];               // coalesced LDG, 2-way-conflict STS (ok)
    }
    __syncthreads();

    int warp = threadIdx.x >> 5, lane = threadIdx.x & 31;
    int pos0 = half * 18 + warp * 2;

    int oh0 = pos0 / 6, ow0 = pos0 % 6;
    int oh1 = (pos0 + 1) / 6, ow1 = (pos0 + 1) % 6;
    int ihb0 = oh0 * 8 - 2, iwb0 = ow0 * 8 - 2;
    int ihb1 = oh1 * 8 - 2, iwb1 = ow1 * 8 - 2;

    float2 a0 = {0.f, 0.f}, a1 = {0.f, 0.f};
    #pragma unroll
    for (int kh = 0; kh < 11; kh++) {
        #pragma unroll
        for (int kw = 0; kw < 11; kw++) {
            const float2* wp2 = (const float2*)(sw + (kh * 11 + kw) * 66);
            float2 wv = wp2[lane];
            int ih0 = ihb0 + kh, iw0 = iwb0 + kw;
            if ((unsigned)ih0 < 48u && (unsigned)iw0 < 48u) {
                const float2* ip = (const float2*)(in + (ih0 * 48 + iw0) * 64);
                float2 iv = ip[lane];
                a0.x = fmaf(iv.x, wv.x, a0.x);
                a0.y = fmaf(iv.y, wv.y, a0.y);
            }
            int ih1 = ihb1 + kh, iw1 = iwb1 + kw;
            if ((unsigned)ih1 < 48u && (unsigned)iw1 < 48u) {
                const float2* ip = (const float2*)(in + (ih1 * 48 + iw1) * 64);
                float2 iv = ip[lane];
                a1.x = fmaf(iv.x, wv.x, a1.x);
                a1.y = fmaf(iv.y, wv.y, a1.y);
            }
        }
    }
    float acc0 = a0.x + a0.y;
    float acc1 = a1.x + a1.y;
    #pragma unroll
    for (int off = 16; off; off >>= 1) {
        acc0 += __shfl_xor_sync(0xffffffffu, acc0, off);
        acc1 += __shfl_xor_sync(0xffffffffu, acc1, off);
    }
    if (lane == 0) {
        float bias = (t ? bk : bq)[oc];
        float* dst = (t ? g_kd : g_qd) + (b * 64 + oc) * MM;
        float x0 = acc0 + bias;
        dst[pos0] = 0.5f * x0 * (1.0f + erff(x0 * 0.7071067811865476f));
        float x1 = acc1 + bias;
        dst[pos0 + 1] = 0.5f * x1 * (1.0f + erff(x1 * 0.7071067811865476f));
    }
}

// ---------------- kernel C: dots[b,h,i36,j36] ----------------
__global__ void dots_kernel() {
    int idx = blockIdx.x * 256 + threadIdx.x;
    if (idx >= NB * HEADS * MM * MM) return;
    int j  = idx % 36;
    int i  = (idx / 36) % 36;
    int bh = idx / (36 * 36);
    int b = bh >> 3, hd = bh & 7;
    const float* qd = g_qd + (b * 64 + hd * 8) * MM;
    const float* kd = g_kd + (b * 64 + hd * 8) * MM;
    float s = 0.f;
    #pragma unroll
    for (int c = 0; c < 8; c++) s = fmaf(qd[c * MM + i], kd[c * MM + j], s);
    g_dots[idx] = s * SCALE;
}

// ---------------- kernel D: fused pos-logits + softmax + attn@v (r5 design) ----------------
// one warp per 4 consecutive output rows; grid 1152 blocks, 256 threads

#define FMA2(d, a, b, c) asm("fma.rn.f32x2 %0, %1, %2, %3;" : "=l"(d) : "l"(a), "l"(b), "l"(c))
#define PACK2(out, x)    asm("mov.b64 %0, {%1, %1};" : "=l"(out) : "r"(x))
#define UNPK2(lo, hi, in) asm("mov.b64 {%0, %1}, %2;" : "=r"(lo), "=r"(hi) : "l"(in))

// per-warp smem floats: sQ 32 | sD 40 | sA 192 | sB 192 | eC2 576 = 1032
#define WSH 1032

__global__ void __launch_bounds__(256, 3)
attn_kernel(const float* __restrict__ pos_h, const float* __restrict__ pos_w,
            float* __restrict__ out) {
    __shared__ float sh[8][WSH];
    int warp = threadIdx.x >> 5, lane = threadIdx.x & 31;
    int w = blockIdx.x * 8 + warp;              // global warp id < 9216
    int bh = w / 576;
    int i0 = (w % 576) * 4;
    int b = bh >> 3, hd = bh & 7;

    float* sQ  = sh[warp];          // 32
    float* sD  = sh[warp] + 32;     // 40  (later reused as sumB16[12])
    float* sA  = sh[warp] + 72;     // 4*48
    float* sB  = sh[warp] + 264;    // 4*48
    float* eC2 = sh[warp] + 456;    // 144*4, layout [s][r]
    float* sB2 = sh[warp] + 72;     // alias sA: [w][r]
    float* smB = sh[warp] + 32;     // alias sD: sumB16[r*3+phi]

    // stage q for 4 rows
    {
        int r = lane >> 3, c = lane & 7;
        sQ[lane] = g_qt[((size_t)(b * HW + i0 + r)) * 64 + hd * 8 + c];
    }
    // raw D row
    {
        const float* dsrc = g_dots + ((b * HEADS + hd) * MM + (i0 >> 6)) * MM;
        for (int t = lane; t < 36; t += 32) sD[t] = dsrc[t];
    }
    __syncwarp();

    // raw A/B for 4 rows
    for (int jh = lane; jh < 48; jh += 32) {
        #pragma unroll
        for (int r = 0; r < 4; r++) {
            float a = 0.f, bb = 0.f;
            #pragma unroll
            for (int c = 0; c < 8; c++) {
                float qv = sQ[r * 8 + c];
                a  = fmaf(qv, __ldg(&pos_h[c * 48 + jh]), a);
                bb = fmaf(qv, __ldg(&pos_w[c * 48 + jh]), bb);
            }
            sA[r * 48 + jh] = a;
            sB[r * 48 + jh] = bb;
        }
    }
    __syncwarp();

    // per-component maxes
    float mA[4], mB[4], mD = -1e30f;
    #pragma unroll
    for (int r = 0; r < 4; r++) { mA[r] = -1e30f; mB[r] = -1e30f; }
    for (int t = lane; t < 48; t += 32) {
        #pragma unroll
        for (int r = 0; r < 4; r++) {
            mA[r] = fmaxf(mA[r], sA[r * 48 + t]);
            mB[r] = fmaxf(mB[r], sB[r * 48 + t]);
        }
    }
    for (int t = lane; t < 36; t += 32) mD = fmaxf(mD, sD[t]);
    #pragma unroll
    for (int off = 16; off; off >>= 1) {
        mD = fmaxf(mD, __shfl_xor_sync(0xffffffffu, mD, off));
        #pragma unroll
        for (int r = 0; r < 4; r++) {
            mA[r] = fmaxf(mA[r], __shfl_xor_sync(0xffffffffu, mA[r], off));
            mB[r] = fmaxf(mB[r], __shfl_xor_sync(0xffffffffu, mB[r], off));
        }
    }
    __syncwarp();

    // exponentiate components in place
    for (int t = lane; t < 36; t += 32) sD[t] = __expf(sD[t] - mD);
    for (int t = lane; t < 48; t += 32) {
        #pragma unroll
        for (int r = 0; r < 4; r++) {
            sA[r * 48 + t] = __expf(sA[r * 48 + t] - mA[r]);
            sB[r * 48 + t] = __expf(sB[r * 48 + t] - mB[r]);
        }
    }
    __syncwarp();

    // eC2[s][r] = eA[r][s/3] * eD[s>>2]   (s = j>>4; 16-segments align with both maps)
    for (int s = lane; s < 144; s += 32) {
        float d = sD[s >> 2];
        int jh = s / 3;
        float4 v;
        v.x = sA[0 * 48 + jh] * d;
        v.y = sA[1 * 48 + jh] * d;
        v.z = sA[2 * 48 + jh] * d;
        v.w = sA[3 * 48 + jh] * d;
        *(float4*)&eC2[s * 4] = v;
    }
    __syncwarp();

    // sumB16[r][phi] = sum_{u<16} eB[r][16*phi+u]  (into sD region; sD dead now)
    if (lane < 12) {
        int r = lane / 3, phi = lane % 3;
        float s16 = 0.f;
        #pragma unroll
        for (int u = 0; u < 16; u++) s16 += sB[r * 48 + phi * 16 + u];
        smB[r * 3 + phi] = s16;
    }
    __syncwarp();

    // sB2[w][r] = eB[r][w]  (overwrites sA region — safe, eC2 already built)
    for (int t = lane; t < 48; t += 32) {
        float4 v;
        v.x = sB[0 * 48 + t];
        v.y = sB[1 * 48 + t];
        v.z = sB[2 * 48 + t];
        v.w = sB[3 * 48 + t];
        *(float4*)&sB2[t * 4] = v;
    }
    __syncwarp();

    // per-lane partial row sums: ssum[r] = sum_s eC2[s][r] * sumB16[r][s%3]
    float ssum[4] = {0.f, 0.f, 0.f, 0.f};
    for (int s = lane; s < 144; s += 32) {
        int phi = s % 3;
        float4 c = *(const float4*)&eC2[s * 4];
        ssum[0] = fmaf(c.x, smB[0 + phi], ssum[0]);
        ssum[1] = fmaf(c.y, smB[3 + phi], ssum[1]);
        ssum[2] = fmaf(c.z, smB[6 + phi], ssum[2]);
        ssum[3] = fmaf(c.w, smB[9 + phi], ssum[3]);
    }

    const ulonglong2* vlo = (const ulonglong2*)g_vlo4 + (size_t)(b * HEADS + hd) * HW;
    const ulonglong2* vhi = (const ulonglong2*)g_vhi4 + (size_t)(b * HEADS + hd) * HW;

    unsigned long long acc[4][4];
    #pragma unroll
    for (int r = 0; r < 4; r++)
        #pragma unroll
        for (int k = 0; k < 4; k++) acc[r][k] = 0ull;

    int j = lane;
    int s1 = lane >> 4;                       // j>>4; partner j+32 -> s1+2
    int jw1 = lane;                           // j % 48 (lane < 48)
    int jw2 = (lane >= 16) ? lane - 16 : lane + 32;   // (j+32) % 48

    #pragma unroll 1
    for (int t = 0; t < 36; t++) {
        ulonglong2 La = vlo[j],      Ha = vhi[j];
        ulonglong2 Lb = vlo[j + 32], Hb = vhi[j + 32];
        float4 c1 = *(const float4*)&eC2[s1 * 4];
        float4 c2 = *(const float4*)&eC2[(s1 + 2) * 4];
        float4 b1 = *(const float4*)&sB2[jw1 * 4];
        float4 b2 = *(const float4*)&sB2[jw2 * 4];

        float pa0 = c1.x * b1.x, pb0 = c2.x * b2.x;
        float pa1 = c1.y * b1.y, pb1 = c2.y * b2.y;
        float pa2 = c1.z * b1.z, pb2 = c2.z * b2.z;
        float pa3 = c1.w * b1.w, pb3 = c2.w * b2.w;

        unsigned long long qa0, qa1, qa2, qa3, qb0, qb1, qb2, qb3;
        PACK2(qa0, __float_as_uint(pa0)); PACK2(qb0, __float_as_uint(pb0));
        PACK2(qa1, __float_as_uint(pa1)); PACK2(qb1, __float_as_uint(pb1));
        PACK2(qa2, __float_as_uint(pa2)); PACK2(qb2, __float_as_uint(pb2));
        PACK2(qa3, __float_as_uint(pa3)); PACK2(qb3, __float_as_uint(pb3));

        FMA2(acc[0][0], qa0, La.x, acc[0][0]); FMA2(acc[0][1], qa0, La.y, acc[0][1]);
        FMA2(acc[0][2], qa0, Ha.x, acc[0][2]); FMA2(acc[0][3], qa0, Ha.y, acc[0][3]);
        FMA2(acc[1][0], qa1, La.x, acc[1][0]); FMA2(acc[1][1], qa1, La.y, acc[1][1]);
        FMA2(acc[1][2], qa1, Ha.x, acc[1][2]); FMA2(acc[1][3], qa1, Ha.y, acc[1][3]);
        FMA2(acc[2][0], qa2, La.x, acc[2][0]); FMA2(acc[2][1], qa2, La.y, acc[2][1]);
        FMA2(acc[2][2], qa2, Ha.x, acc[2][2]); FMA2(acc[2][3], qa2, Ha.y, acc[2][3]);
        FMA2(acc[3][0], qa3, La.x, acc[3][0]); FMA2(acc[3][1], qa3, La.y, acc[3][1]);
        FMA2(acc[3][2], qa3, Ha.x, acc[3][2]); FMA2(acc[3][3], qa3, Ha.y, acc[3][3]);

        FMA2(acc[0][0], qb0, Lb.x, acc[0][0]); FMA2(acc[0][1], qb0, Lb.y, acc[0][1]);
        FMA2(acc[0][2], qb0, Hb.x, acc[0][2]); FMA2(acc[0][3], qb0, Hb.y, acc[0][3]);
        FMA2(acc[1][0], qb1, Lb.x, acc[1][0]); FMA2(acc[1][1], qb1, Lb.y, acc[1][1]);
        FMA2(acc[1][2], qb1, Hb.x, acc[1][2]); FMA2(acc[1][3], qb1, Hb.y, acc[1][3]);
        FMA2(acc[2][0], qb2, Lb.x, acc[2][0]); FMA2(acc[2][1], qb2, Lb.y, acc[2][1]);
        FMA2(acc[2][2], qb2, Hb.x, acc[2][2]); FMA2(acc[2][3], qb2, Hb.y, acc[2][3]);
        FMA2(acc[3][0], qb3, Lb.x, acc[3][0]); FMA2(acc[3][1], qb3, Lb.y, acc[3][1]);
        FMA2(acc[3][2], qb3, Hb.x, acc[3][2]); FMA2(acc[3][3], qb3, Hb.y, acc[3][3]);

        j += 64;
        s1 += 4;
        jw1 += 16; if (jw1 >= 48) jw1 -= 48;
        jw2 += 16; if (jw2 >= 48) jw2 -= 48;
    }

    // reduce + write 4 rows
    #pragma unroll
    for (int r = 0; r < 4; r++) {
        float f0, f1, f2, f3, f4, f5, f6, f7;
        unsigned u0, u1;
        UNPK2(u0, u1, acc[r][0]); f0 = __uint_as_float(u0); f1 = __uint_as_float(u1);
        UNPK2(u0, u1, acc[r][1]); f2 = __uint_as_float(u0); f3 = __uint_as_float(u1);
        UNPK2(u0, u1, acc[r][2]); f4 = __uint_as_float(u0); f5 = __uint_as_float(u1);
        UNPK2(u0, u1, acc[r][3]); f6 = __uint_as_float(u0); f7 = __uint_as_float(u1);
        float sv = ssum[r];
        #pragma unroll
        for (int off = 16; off; off >>= 1) {
            sv += __shfl_xor_sync(0xffffffffu, sv, off);
            f0 += __shfl_xor_sync(0xffffffffu, f0, off);
            f1 += __shfl_xor_sync(0xffffffffu, f1, off);
            f2 += __shfl_xor_sync(0xffffffffu, f2, off);
            f3 += __shfl_xor_sync(0xffffffffu, f3, off);
            f4 += __shfl_xor_sync(0xffffffffu, f4, off);
            f5 += __shfl_xor_sync(0xffffffffu, f5, off);
            f6 += __shfl_xor_sync(0xffffffffu, f6, off);
            f7 += __shfl_xor_sync(0xffffffffu, f7, off);
        }
        float rr = f0;
        if (lane == 1) rr = f1;
        if (lane == 2) rr = f2;
        if (lane == 3) rr = f3;
        if (lane == 4) rr = f4;
        if (lane == 5) rr = f5;
        if (lane == 6) rr = f6;
        if (lane == 7) rr = f7;
        if (lane < 8)
            out[((size_t)(b * 64) + hd * 8 + lane) * HW + i0 + r] = rr / sv;
    }
}

// ---------------- launch ----------------
extern "C" void kernel_launch(void* const* d_in, const int* in_sizes, int n_in,
                              void* d_out, int out_size) {
    const float* f    = (const float*)d_in[0];
    const float* wqkv = (const float*)d_in[1];
    const float* wq   = (const float*)d_in[2];
    const float* bq   = (const float*)d_in[3];
    const float* wk   = (const float*)d_in[4];
    const float* bk   = (const float*)d_in[5];
    const float* ph   = (const float*)d_in[6];
    const float* pw   = (const float*)d_in[7];
    float* out = (float*)d_out;

    qkv_kernel<<<144, 256>>>(f, wqkv);
    conv_kernel<<<512, 288>>>(wq, bq, wk, bk);
    dots_kernel<<<81, 256>>>();
    attn_kernel<<<1152, 256>>>(ph, pw, out);
}

// round 9
// speedup vs baseline: 1.6729x; 1.1127x over previous
#include <cuda_runtime.h>
#include <math.h>
#include <stdint.h>

#define NB 2
#define NC 64
#define HW 2304
#define INNER 64
#define HEADS 8
#define DH 8
#define MM 36
#define SCALE 0.35355339059327373f

// ---------------- scratch (device globals; no allocation allowed) ----------------
__device__ float g_qt[NB * HW * INNER];          // q channel-last: [b][p][c]
__device__ float g_kt[NB * HW * INNER];          // k channel-last: [b][p][c]
__device__ float4 g_vlo4[NB * HEADS * HW];       // v channels 0..3:  [b][head][j]
__device__ float4 g_vhi4[NB * HEADS * HW];       // v channels 4..7
__device__ float g_qd[NB * INNER * MM];          // conv+gelu(q): [b][oc][pos36]
__device__ float g_kd[NB * INNER * MM];
__device__ float g_dots[NB * HEADS * MM * MM];   // [b][head][i36][j36]

// ---------------- kernel A: 1x1 conv qkv + layout transforms ----------------
__global__ void qkv_kernel(const float* __restrict__ f, const float* __restrict__ wqkv) {
    __shared__ float sF[64 * 32];   // [c][pp]
    int b = blockIdx.x / 72;
    int p0 = (blockIdx.x % 72) * 32;

    for (int idx = threadIdx.x; idx < 64 * 32; idx += 256) {
        int c = idx >> 5, pp = idx & 31;
        sF[idx] = f[(b * 64 + c) * HW + p0 + pp];
    }
    __syncthreads();

    int pp = threadIdx.x & 31;
    int o0 = threadIdx.x >> 5;   // 0..7
    int p = p0 + pp;
    for (int o = o0; o < 192; o += 8) {
        const float* wr = wqkv + o * 64;
        float a0 = 0.f, a1 = 0.f, a2 = 0.f, a3 = 0.f;
        #pragma unroll
        for (int c = 0; c < 16; c++) {
            a0 = fmaf(__ldg(&wr[c]),      sF[c * 32 + pp],        a0);
            a1 = fmaf(__ldg(&wr[c + 16]), sF[(c + 16) * 32 + pp], a1);
            a2 = fmaf(__ldg(&wr[c + 32]), sF[(c + 32) * 32 + pp], a2);
            a3 = fmaf(__ldg(&wr[c + 48]), sF[(c + 48) * 32 + pp], a3);
        }
        float acc = (a0 + a1) + (a2 + a3);
        if (o < 64) {
            g_qt[(b * HW + p) * 64 + o] = acc;
        } else if (o < 128) {
            g_kt[(b * HW + p) * 64 + (o - 64)] = acc;
        } else {
            int oi = o - 128;
            int hd = oi >> 3, c = oi & 7;
            float* vout = (float*)(c < 4 ? g_vlo4 : g_vhi4);
            vout[((size_t)(b * HEADS + hd) * HW + p) * 4 + (c & 3)] = acc;
        }
    }
}

// ---------------- kernel B: 11x11 stride-8 pad-2 conv + exact GELU ----------------
__global__ void conv_kernel(const float* __restrict__ wq, const float* __restrict__ bq,
                            const float* __restrict__ wk, const float* __restrict__ bk) {
    int bid = blockIdx.x;
    int half = bid & 1;
    int oc = (bid >> 1) & 63;
    int b  = (bid >> 7) & 1;
    int t  = bid >> 8;

    const float* wsrc = (t ? wk : wq) + oc * 64 * 121;   // layout [ic][tap], linear
    const float* in   = (t ? g_kt : g_qt) + b * HW * 64;

    __shared__ __align__(16) float sw[121 * 66];
    for (int idx = threadIdx.x; idx < 121 * 64; idx += 288) {
        int ic = idx / 121, tap = idx % 121;
        sw[tap * 66 + ic] = wsrc[idx];
    }
    __syncthreads();

    int warp = threadIdx.x >> 5, lane = threadIdx.x & 31;
    int pos0 = half * 18 + warp * 2;

    int oh0 = pos0 / 6, ow0 = pos0 % 6;
    int oh1 = (pos0 + 1) / 6, ow1 = (pos0 + 1) % 6;
    int ihb0 = oh0 * 8 - 2, iwb0 = ow0 * 8 - 2;
    int ihb1 = oh1 * 8 - 2, iwb1 = ow1 * 8 - 2;

    float2 a0 = {0.f, 0.f}, a1 = {0.f, 0.f};
    #pragma unroll
    for (int kh = 0; kh < 11; kh++) {
        #pragma unroll
        for (int kw = 0; kw < 11; kw++) {
            const float2* wp2 = (const float2*)(sw + (kh * 11 + kw) * 66);
            float2 wv = wp2[lane];
            int ih0 = ihb0 + kh, iw0 = iwb0 + kw;
            if ((unsigned)ih0 < 48u && (unsigned)iw0 < 48u) {
                const float2* ip = (const float2*)(in + (ih0 * 48 + iw0) * 64);
                float2 iv = ip[lane];
                a0.x = fmaf(iv.x, wv.x, a0.x);
                a0.y = fmaf(iv.y, wv.y, a0.y);
            }
            int ih1 = ihb1 + kh, iw1 = iwb1 + kw;
            if ((unsigned)ih1 < 48u && (unsigned)iw1 < 48u) {
                const float2* ip = (const float2*)(in + (ih1 * 48 + iw1) * 64);
                float2 iv = ip[lane];
                a1.x = fmaf(iv.x, wv.x, a1.x);
                a1.y = fmaf(iv.y, wv.y, a1.y);
            }
        }
    }
    float acc0 = a0.x + a0.y;
    float acc1 = a1.x + a1.y;
    #pragma unroll
    for (int off = 16; off; off >>= 1) {
        acc0 += __shfl_xor_sync(0xffffffffu, acc0, off);
        acc1 += __shfl_xor_sync(0xffffffffu, acc1, off);
    }
    if (lane == 0) {
        float bias = (t ? bk : bq)[oc];
        float* dst = (t ? g_kd : g_qd) + (b * 64 + oc) * MM;
        float x0 = acc0 + bias;
        dst[pos0] = 0.5f * x0 * (1.0f + erff(x0 * 0.7071067811865476f));
        float x1 = acc1 + bias;
        dst[pos0 + 1] = 0.5f * x1 * (1.0f + erff(x1 * 0.7071067811865476f));
    }
}

// ---------------- kernel C: dots[b,h,i36,j36] ----------------
__global__ void dots_kernel() {
    int idx = blockIdx.x * 256 + threadIdx.x;
    if (idx >= NB * HEADS * MM * MM) return;
    int j  = idx % 36;
    int i  = (idx / 36) % 36;
    int bh = idx / (36 * 36);
    int b = bh >> 3, hd = bh & 7;
    const float* qd = g_qd + (b * 64 + hd * 8) * MM;
    const float* kd = g_kd + (b * 64 + hd * 8) * MM;
    float s = 0.f;
    #pragma unroll
    for (int c = 0; c < 8; c++) s = fmaf(qd[c * MM + i], kd[c * MM + j], s);
    g_dots[idx] = s * SCALE;
}

// ---------------- kernel D: fused pos-logits + softmax + attn@v ----------------
// one warp per 8 consecutive output rows (same b,head, same D-row since i0%8==0)
// grid: 36864/8/4 = 1152 blocks, 128 threads (4 warps)

#define FMA2(d, a, b, c) asm("fma.rn.f32x2 %0, %1, %2, %3;" : "=l"(d) : "l"(a), "l"(b), "l"(c))
#define PACK2(out, x)    asm("mov.b64 %0, {%1, %1};" : "=l"(out) : "r"(x))
#define UNPK2(lo, hi, in) asm("mov.b64 {%0, %1}, %2;" : "=r"(lo), "=r"(hi) : "l"(in))

// per-warp smem floats:
//  0    sQ[64]      (dead after sA/sB built; smB[24] aliased here)
//  64   sD[40]
//  104  sA[8*48]
//  488  sB[8*48]
//  872  eC2[144*8]  (layout [s][r], 16B-aligned: 872*4 % 16 == 0)
//  2024 rsum[8]
#define WSH 2032

__global__ void __launch_bounds__(128, 4)
attn_kernel(const float* __restrict__ pos_h, const float* __restrict__ pos_w,
            float* __restrict__ out) {
    __shared__ float sh[4][WSH];
    int warp = threadIdx.x >> 5, lane = threadIdx.x & 31;
    int w = blockIdx.x * 4 + warp;              // global warp id < 4608
    int bh = w / 288;                           // 2304/8 = 288 row-groups per (b,h)
    int i0 = (w % 288) * 8;
    int b = bh >> 3, hd = bh & 7;

    float* sQ   = sh[warp];          // 64
    float* sD   = sh[warp] + 64;     // 40
    float* sA   = sh[warp] + 104;    // 8*48
    float* sB   = sh[warp] + 488;    // 8*48
    float* eC2  = sh[warp] + 872;    // 144*8, [s][r]
    float* rsum = sh[warp] + 2024;   // 8
    float* smB  = sh[warp];          // alias sQ: sumB16[r*3+phi], 24

    // stage q for 8 rows: sQ[r*8+c]
    {
        int t = lane;
        sQ[t] = g_qt[((size_t)(b * HW + i0 + (t >> 3))) * 64 + hd * 8 + (t & 7)];
        t += 32;
        sQ[t] = g_qt[((size_t)(b * HW + i0 + (t >> 3))) * 64 + hd * 8 + (t & 7)];
    }
    // raw D row (i0..i0+7 share i0>>6 since i0 % 8 == 0)
    {
        const float* dsrc = g_dots + ((b * HEADS + hd) * MM + (i0 >> 6)) * MM;
        for (int t = lane; t < 36; t += 32) sD[t] = dsrc[t];
    }
    __syncwarp();

    // raw A/B for 8 rows
    for (int jh = lane; jh < 48; jh += 32) {
        float phv[8], pwv[8];
        #pragma unroll
        for (int c = 0; c < 8; c++) {
            phv[c] = __ldg(&pos_h[c * 48 + jh]);
            pwv[c] = __ldg(&pos_w[c * 48 + jh]);
        }
        #pragma unroll
        for (int r = 0; r < 8; r++) {
            float a = 0.f, bb = 0.f;
            #pragma unroll
            for (int c = 0; c < 8; c++) {
                float qv = sQ[r * 8 + c];
                a  = fmaf(qv, phv[c], a);
                bb = fmaf(qv, pwv[c], bb);
            }
            sA[r * 48 + jh] = a;
            sB[r * 48 + jh] = bb;
        }
    }
    __syncwarp();

    // per-component maxes
    float mA[8], mB[8], mD = -1e30f;
    #pragma unroll
    for (int r = 0; r < 8; r++) { mA[r] = -1e30f; mB[r] = -1e30f; }
    for (int t = lane; t < 48; t += 32) {
        #pragma unroll
        for (int r = 0; r < 8; r++) {
            mA[r] = fmaxf(mA[r], sA[r * 48 + t]);
            mB[r] = fmaxf(mB[r], sB[r * 48 + t]);
        }
    }
    for (int t = lane; t < 36; t += 32) mD = fmaxf(mD, sD[t]);
    #pragma unroll
    for (int off = 16; off; off >>= 1) {
        mD = fmaxf(mD, __shfl_xor_sync(0xffffffffu, mD, off));
        #pragma unroll
        for (int r = 0; r < 8; r++) {
            mA[r] = fmaxf(mA[r], __shfl_xor_sync(0xffffffffu, mA[r], off));
            mB[r] = fmaxf(mB[r], __shfl_xor_sync(0xffffffffu, mB[r], off));
        }
    }
    __syncwarp();

    // exponentiate in place
    for (int t = lane; t < 36; t += 32) sD[t] = __expf(sD[t] - mD);
    for (int t = lane; t < 48; t += 32) {
        #pragma unroll
        for (int r = 0; r < 8; r++) {
            sA[r * 48 + t] = __expf(sA[r * 48 + t] - mA[r]);
            sB[r * 48 + t] = __expf(sB[r * 48 + t] - mB[r]);
        }
    }
    __syncwarp();

    // eC2[s][r] = eA[r][s/3] * eD[s>>2]
    for (int s = lane; s < 144; s += 32) {
        float d = sD[s >> 2];
        int jh = s / 3;
        float4 v0, v1;
        v0.x = sA[0 * 48 + jh] * d;  v0.y = sA[1 * 48 + jh] * d;
        v0.z = sA[2 * 48 + jh] * d;  v0.w = sA[3 * 48 + jh] * d;
        v1.x = sA[4 * 48 + jh] * d;  v1.y = sA[5 * 48 + jh] * d;
        v1.z = sA[6 * 48 + jh] * d;  v1.w = sA[7 * 48 + jh] * d;
        *(float4*)&eC2[s * 8]     = v0;
        *(float4*)&eC2[s * 8 + 4] = v1;
    }
    __syncwarp();

    // register b-values: jw = (lane + 32t) % 48 has period 3 in t
    int w0 = lane;
    int w1 = (lane < 16) ? lane + 32 : lane - 16;
    int w2 = lane + 16;
    float bva[8], bvb[8], bvc[8];
    #pragma unroll
    for (int r = 0; r < 8; r++) {
        bva[r] = sB[r * 48 + w0];
        bvb[r] = sB[r * 48 + w1];
        bvc[r] = sB[r * 48 + w2];
    }

    // sumB16[r][phi] into smB (sQ dead)
    if (lane < 24) {
        int r = lane / 3, phi = lane % 3;
        float s16 = 0.f;
        #pragma unroll
        for (int u = 0; u < 16; u++) s16 += sB[r * 48 + phi * 16 + u];
        smB[r * 3 + phi] = s16;
    }
    __syncwarp();

    // row sums: ssum[r] = sum_s eC2[s][r] * sumB16[r][s%3]; reduce and park in rsum
    {
        float ssum[8] = {0.f, 0.f, 0.f, 0.f, 0.f, 0.f, 0.f, 0.f};
        for (int s = lane; s < 144; s += 32) {
            int phi = s % 3;
            float4 c0 = *(const float4*)&eC2[s * 8];
            float4 c1 = *(const float4*)&eC2[s * 8 + 4];
            ssum[0] = fmaf(c0.x, smB[0 + phi],  ssum[0]);
            ssum[1] = fmaf(c0.y, smB[3 + phi],  ssum[1]);
            ssum[2] = fmaf(c0.z, smB[6 + phi],  ssum[2]);
            ssum[3] = fmaf(c0.w, smB[9 + phi],  ssum[3]);
            ssum[4] = fmaf(c1.x, smB[12 + phi], ssum[4]);
            ssum[5] = fmaf(c1.y, smB[15 + phi], ssum[5]);
            ssum[6] = fmaf(c1.z, smB[18 + phi], ssum[6]);
            ssum[7] = fmaf(c1.w, smB[21 + phi], ssum[7]);
        }
        #pragma unroll
        for (int off = 16; off; off >>= 1) {
            #pragma unroll
            for (int r = 0; r < 8; r++)
                ssum[r] += __shfl_xor_sync(0xffffffffu, ssum[r], off);
        }
        if (lane == 0) {
            #pragma unroll
            for (int r = 0; r < 8; r++) rsum[r] = ssum[r];
        }
    }
    __syncwarp();

    const ulonglong2* vlo = (const ulonglong2*)g_vlo4 + (size_t)(b * HEADS + hd) * HW;
    const ulonglong2* vhi = (const ulonglong2*)g_vhi4 + (size_t)(b * HEADS + hd) * HW;

    unsigned long long acc[8][4];
    #pragma unroll
    for (int r = 0; r < 8; r++)
        #pragma unroll
        for (int k = 0; k < 4; k++) acc[r][k] = 0ull;

    // main loop: j = lane + 32t, t = 0..71; 3-phase unroll; s = (lane>>4) + 2t
    int j = lane;
    int s = lane >> 4;

#define STEP(JOFS, SOFS, BV) { \
        ulonglong2 L = vlo[j + (JOFS)]; \
        ulonglong2 H = vhi[j + (JOFS)]; \
        float4 c0 = *(const float4*)&eC2[(s + (SOFS)) * 8]; \
        float4 c1 = *(const float4*)&eC2[(s + (SOFS)) * 8 + 4]; \
        unsigned long long q0, q1, q2, q3, q4, q5, q6, q7; \
        PACK2(q0, __float_as_uint(c0.x * BV[0])); \
        PACK2(q1, __float_as_uint(c0.y * BV[1])); \
        PACK2(q2, __float_as_uint(c0.z * BV[2])); \
        PACK2(q3, __float_as_uint(c0.w * BV[3])); \
        PACK2(q4, __float_as_uint(c1.x * BV[4])); \
        PACK2(q5, __float_as_uint(c1.y * BV[5])); \
        PACK2(q6, __float_as_uint(c1.z * BV[6])); \
        PACK2(q7, __float_as_uint(c1.w * BV[7])); \
        FMA2(acc[0][0], q0, L.x, acc[0][0]); FMA2(acc[0][1], q0, L.y, acc[0][1]); \
        FMA2(acc[0][2], q0, H.x, acc[0][2]); FMA2(acc[0][3], q0, H.y, acc[0][3]); \
        FMA2(acc[1][0], q1, L.x, acc[1][0]); FMA2(acc[1][1], q1, L.y, acc[1][1]); \
        FMA2(acc[1][2], q1, H.x, acc[1][2]); FMA2(acc[1][3], q1, H.y, acc[1][3]); \
        FMA2(acc[2][0], q2, L.x, acc[2][0]); FMA2(acc[2][1], q2, L.y, acc[2][1]); \
        FMA2(acc[2][2], q2, H.x, acc[2][2]); FMA2(acc[2][3], q2, H.y, acc[2][3]); \
        FMA2(acc[3][0], q3, L.x, acc[3][0]); FMA2(acc[3][1], q3, L.y, acc[3][1]); \
        FMA2(acc[3][2], q3, H.x, acc[3][2]); FMA2(acc[3][3], q3, H.y, acc[3][3]); \
        FMA2(acc[4][0], q4, L.x, acc[4][0]); FMA2(acc[4][1], q4, L.y, acc[4][1]); \
        FMA2(acc[4][2], q4, H.x, acc[4][2]); FMA2(acc[4][3], q4, H.y, acc[4][3]); \
        FMA2(acc[5][0], q5, L.x, acc[5][0]); FMA2(acc[5][1], q5, L.y, acc[5][1]); \
        FMA2(acc[5][2], q5, H.x, acc[5][2]); FMA2(acc[5][3], q5, H.y, acc[5][3]); \
        FMA2(acc[6][0], q6, L.x, acc[6][0]); FMA2(acc[6][1], q6, L.y, acc[6][1]); \
        FMA2(acc[6][2], q6, H.x, acc[6][2]); FMA2(acc[6][3], q6, H.y, acc[6][3]); \
        FMA2(acc[7][0], q7, L.x, acc[7][0]); FMA2(acc[7][1], q7, L.y, acc[7][1]); \
        FMA2(acc[7][2], q7, H.x, acc[7][2]); FMA2(acc[7][3], q7, H.y, acc[7][3]); \
    }

    #pragma unroll 1
    for (int tt = 0; tt < 24; tt++) {
        STEP(0,  0, bva)
        STEP(32, 2, bvb)
        STEP(64, 4, bvc)
        j += 96;
        s += 6;
    }
#undef STEP

    // reduce + write 8 rows
    #pragma unroll
    for (int r = 0; r < 8; r++) {
        float f0, f1, f2, f3, f4, f5, f6, f7;
        unsigned u0, u1;
        UNPK2(u0, u1, acc[r][0]); f0 = __uint_as_float(u0); f1 = __uint_as_float(u1);
        UNPK2(u0, u1, acc[r][1]); f2 = __uint_as_float(u0); f3 = __uint_as_float(u1);
        UNPK2(u0, u1, acc[r][2]); f4 = __uint_as_float(u0); f5 = __uint_as_float(u1);
        UNPK2(u0, u1, acc[r][3]); f6 = __uint_as_float(u0); f7 = __uint_as_float(u1);
        #pragma unroll
        for (int off = 16; off; off >>= 1) {
            f0 += __shfl_xor_sync(0xffffffffu, f0, off);
            f1 += __shfl_xor_sync(0xffffffffu, f1, off);
            f2 += __shfl_xor_sync(0xffffffffu, f2, off);
            f3 += __shfl_xor_sync(0xffffffffu, f3, off);
            f4 += __shfl_xor_sync(0xffffffffu, f4, off);
            f5 += __shfl_xor_sync(0xffffffffu, f5, off);
            f6 += __shfl_xor_sync(0xffffffffu, f6, off);
            f7 += __shfl_xor_sync(0xffffffffu, f7, off);
        }
        float rr = f0;
        if (lane == 1) rr = f1;
        if (lane == 2) rr = f2;
        if (lane == 3) rr = f3;
        if (lane == 4) rr = f4;
        if (lane == 5) rr = f5;
        if (lane == 6) rr = f6;
        if (lane == 7) rr = f7;
        if (lane < 8)
            out[((size_t)(b * 64) + hd * 8 + lane) * HW + i0 + r] = rr / rsum[r];
    }
}

// ---------------- launch ----------------
extern "C" void kernel_launch(void* const* d_in, const int* in_sizes, int n_in,
                              void* d_out, int out_size) {
    const float* f    = (const float*)d_in[0];
    const float* wqkv = (const float*)d_in[1];
    const float* wq   = (const float*)d_in[2];
    const float* bq   = (const float*)d_in[3];
    const float* wk   = (const float*)d_in[4];
    const float* bk   = (const float*)d_in[5];
    const float* ph   = (const float*)d_in[6];
    const float* pw   = (const float*)d_in[7];
    float* out = (float*)d_out;

    qkv_kernel<<<144, 256>>>(f, wqkv);
    conv_kernel<<<512, 288>>>(wq, bq, wk, bk);
    dots_kernel<<<81, 256>>>();
    attn_kernel<<<1152, 128>>>(ph, pw, out);
}